// round 1
// baseline (speedup 1.0000x reference)
#include <cuda_runtime.h>

// ---------------- problem constants ----------------
#define NB      2048          // windows*batch
#define NTOK    49            // tokens per window
#define DIMC    512
#define QKV_N   1536
#define NHEAD   16
#define HDIM    32
#define NWIN    64
#define M_TOTAL (NB * NTOK)   // 100352

// ---------------- scratch (no allocs allowed) ----------------
__device__ float g_qkv[(size_t)M_TOTAL * QKV_N];   // 616 MB
__device__ float g_att[(size_t)M_TOTAL * DIMC];    // 205 MB

// ---------------- SGEMM: C = A(MxK) @ B(KxN) + bias, all dims % tile == 0 ----
#define BM 64
#define BN 64
#define BK 32

__global__ void __launch_bounds__(256) sgemm_bias_kernel(
    const float* __restrict__ A, const float* __restrict__ B,
    const float* __restrict__ bias, float* __restrict__ C,
    int M, int N, int K)
{
    __shared__ float As[BK][BM];
    __shared__ float Bs[BK][BN];

    const int tid = threadIdx.x;
    const int tx  = tid & 15;          // n-direction (x4)
    const int ty  = tid >> 4;          // m-direction (x4)
    const int blockM = blockIdx.y * BM;
    const int blockN = blockIdx.x * BN;

    float acc[4][4] = {};

    for (int kt = 0; kt < K; kt += BK) {
        // ---- load A tile (BM x BK), store transposed As[k][m]
        #pragma unroll
        for (int i = 0; i < 2; i++) {
            int f   = tid + i * 256;           // float4 id within 64x32 tile
            int row = f >> 3;
            int c4  = (f & 7) << 2;
            float4 a = *reinterpret_cast<const float4*>(
                &A[(size_t)(blockM + row) * K + kt + c4]);
            As[c4 + 0][row] = a.x;
            As[c4 + 1][row] = a.y;
            As[c4 + 2][row] = a.z;
            As[c4 + 3][row] = a.w;
        }
        // ---- load B tile (BK x BN)
        #pragma unroll
        for (int i = 0; i < 2; i++) {
            int f   = tid + i * 256;           // float4 id within 32x64 tile
            int row = f >> 4;
            int c4  = (f & 15) << 2;
            *reinterpret_cast<float4*>(&Bs[row][c4]) =
                *reinterpret_cast<const float4*>(
                    &B[(size_t)(kt + row) * N + blockN + c4]);
        }
        __syncthreads();

        #pragma unroll
        for (int kk = 0; kk < BK; kk++) {
            float4 af = *reinterpret_cast<const float4*>(&As[kk][ty << 2]);
            float4 bf = *reinterpret_cast<const float4*>(&Bs[kk][tx << 2]);
            float av[4] = {af.x, af.y, af.z, af.w};
            float bv[4] = {bf.x, bf.y, bf.z, bf.w};
            #pragma unroll
            for (int i = 0; i < 4; i++)
                #pragma unroll
                for (int j = 0; j < 4; j++)
                    acc[i][j] += av[i] * bv[j];
        }
        __syncthreads();
    }

    // ---- epilogue with bias
    float4 bb = *reinterpret_cast<const float4*>(&bias[blockN + (tx << 2)]);
    float bv[4] = {bb.x, bb.y, bb.z, bb.w};
    #pragma unroll
    for (int i = 0; i < 4; i++) {
        float4 o;
        o.x = acc[i][0] + bv[0];
        o.y = acc[i][1] + bv[1];
        o.z = acc[i][2] + bv[2];
        o.w = acc[i][3] + bv[3];
        *reinterpret_cast<float4*>(
            &C[(size_t)(blockM + (ty << 2) + i) * N + blockN + (tx << 2)]) = o;
    }
}

// ---------------- fused window attention: one block per (window, head) -------
__global__ void __launch_bounds__(128) attn_kernel(
    const float* __restrict__ qkv, const float* __restrict__ mask,
    const float* __restrict__ bias_table, const int* __restrict__ rel_idx,
    float* __restrict__ att)
{
    const int b = blockIdx.x;   // window index 0..2047
    const int h = blockIdx.y;   // head 0..15
    const int tid = threadIdx.x;

    __shared__ float qs[NTOK * HDIM];   // q  [n][d]
    __shared__ float kt[HDIM * NTOK];   // kT [d][m]  (transposed, conflict-free)
    __shared__ float vs[NTOK * HDIM];   // v  [m][d]
    __shared__ float s [NTOK * 50];     // scores / probs, padded row = 50

    const float scale = 0.17677669529663687f;  // 32^-0.5

    // ---- load q, kT, v (49 x 32 each, float4 granularity) ----
    for (int idx = tid; idx < NTOK * 8; idx += 128) {
        int n  = idx >> 3;
        int c4 = (idx & 7) << 2;
        size_t base = ((size_t)(b * NTOK + n)) * QKV_N + h * HDIM + c4;
        float4 qv = *reinterpret_cast<const float4*>(qkv + base);
        float4 kv = *reinterpret_cast<const float4*>(qkv + base + DIMC);
        float4 vv = *reinterpret_cast<const float4*>(qkv + base + 2 * DIMC);
        *reinterpret_cast<float4*>(&qs[n * HDIM + c4]) = qv;
        *reinterpret_cast<float4*>(&vs[n * HDIM + c4]) = vv;
        kt[(c4 + 0) * NTOK + n] = kv.x;
        kt[(c4 + 1) * NTOK + n] = kv.y;
        kt[(c4 + 2) * NTOK + n] = kv.z;
        kt[(c4 + 3) * NTOK + n] = kv.w;
    }
    __syncthreads();

    // ---- S = scale * q kT + bias + mask ----
    const float* mrow = mask + (size_t)(b & (NWIN - 1)) * NTOK * NTOK;
    for (int e = tid; e < NTOK * NTOK; e += 128) {
        int n = e / NTOK;
        int m = e - n * NTOK;
        float acc = 0.f;
        #pragma unroll
        for (int kk = 0; kk < HDIM; kk++)
            acc += qs[n * HDIM + kk] * kt[kk * NTOK + m];
        s[n * 50 + m] = acc * scale
                      + bias_table[rel_idx[e] * NHEAD + h]
                      + mrow[e];
    }
    __syncthreads();

    // ---- row softmax (one thread per row; rows are tiny) ----
    if (tid < NTOK) {
        const int r = tid;
        float mx = -1e30f;
        for (int m = 0; m < NTOK; m++) mx = fmaxf(mx, s[r * 50 + m]);
        float sum = 0.f;
        for (int m = 0; m < NTOK; m++) {
            float e = expf(s[r * 50 + m] - mx);
            s[r * 50 + m] = e;
            sum += e;
        }
        float inv = 1.f / sum;
        for (int m = 0; m < NTOK; m++) s[r * 50 + m] *= inv;
    }
    __syncthreads();

    // ---- O = P @ v  -> att[(b*49+n)*512 + h*32 + d] ----
    for (int o = tid; o < NTOK * HDIM; o += 128) {
        int n = o >> 5;
        int d = o & 31;
        float acc = 0.f;
        #pragma unroll
        for (int m = 0; m < NTOK; m++)
            acc += s[n * 50 + m] * vs[m * HDIM + d];
        att[((size_t)(b * NTOK + n)) * DIMC + h * HDIM + d] = acc;
    }
}

// ---------------- launcher ----------------
extern "C" void kernel_launch(void* const* d_in, const int* in_sizes, int n_in,
                              void* d_out, int out_size)
{
    const float* x          = (const float*)d_in[0];
    const float* mask       = (const float*)d_in[1];
    const float* qkv_w      = (const float*)d_in[2];
    const float* qkv_b      = (const float*)d_in[3];
    const float* proj_w     = (const float*)d_in[4];
    const float* proj_b     = (const float*)d_in[5];
    const float* bias_table = (const float*)d_in[6];
    const int*   rel_idx    = (const int*)d_in[7];
    float* out = (float*)d_out;

    float *qkv, *att;
    cudaGetSymbolAddress((void**)&qkv, g_qkv);
    cudaGetSymbolAddress((void**)&att, g_att);

    // 1) QKV projection: (100352 x 512) @ (512 x 1536) + b
    dim3 g1(QKV_N / BN, M_TOTAL / BM);
    sgemm_bias_kernel<<<g1, 256>>>(x, qkv_w, qkv_b, qkv, M_TOTAL, QKV_N, DIMC);

    // 2) fused window attention per (window, head)
    dim3 g2(NB, NHEAD);
    attn_kernel<<<g2, 128>>>(qkv, mask, bias_table, rel_idx, att);

    // 3) output projection: (100352 x 512) @ (512 x 512) + b
    dim3 g3(DIMC / BN, M_TOTAL / BM);
    sgemm_bias_kernel<<<g3, 256>>>(att, proj_w, proj_b, out, M_TOTAL, DIMC, DIMC);
}

// round 3
// speedup vs baseline: 2.6756x; 2.6756x over previous
#include <cuda_runtime.h>
#include <cuda_bf16.h>
#include <cstdint>

// ---------------- problem constants ----------------
#define NB      2048
#define NTOK    49
#define DIMC    512
#define QKV_N   1536
#define NHEAD   16
#define HDIM    32
#define NWIN    64
#define M_TOTAL (NB * NTOK)   // 100352

// ---------------- scratch (no allocs allowed) ----------------
__device__ float         g_qkv[(size_t)M_TOTAL * QKV_N];
__device__ __nv_bfloat16 g_xhi[(size_t)M_TOTAL * DIMC];
__device__ __nv_bfloat16 g_xlo[(size_t)M_TOTAL * DIMC];
__device__ __nv_bfloat16 g_ahi[(size_t)M_TOTAL * DIMC];
__device__ __nv_bfloat16 g_alo[(size_t)M_TOTAL * DIMC];
__device__ __nv_bfloat16 g_wq_hi[(size_t)QKV_N * DIMC];
__device__ __nv_bfloat16 g_wq_lo[(size_t)QKV_N * DIMC];
__device__ __nv_bfloat16 g_wp_hi[(size_t)DIMC * DIMC];
__device__ __nv_bfloat16 g_wp_lo[(size_t)DIMC * DIMC];

// ---------------- helpers ----------------
__device__ __forceinline__ uint32_t smem_to_u32(const void* p) {
    uint32_t a;
    asm("{ .reg .u64 t; cvta.to.shared.u64 t, %1; cvt.u32.u64 %0, t; }" : "=r"(a) : "l"(p));
    return a;
}
__device__ __forceinline__ void cp_async16(uint32_t saddr, const void* gaddr) {
    asm volatile("cp.async.cg.shared.global [%0], [%1], 16;" :: "r"(saddr), "l"(gaddr));
}
#define CP_COMMIT() asm volatile("cp.async.commit_group;")
#define CP_WAIT0()  asm volatile("cp.async.wait_group 0;")

__device__ __forceinline__ void ldsm4(uint32_t* r, uint32_t addr) {
    asm volatile("ldmatrix.sync.aligned.m8n8.x4.shared.b16 {%0,%1,%2,%3}, [%4];"
                 : "=r"(r[0]), "=r"(r[1]), "=r"(r[2]), "=r"(r[3]) : "r"(addr));
}
__device__ __forceinline__ void mma16816(float* d, const uint32_t* a,
                                         uint32_t b0, uint32_t b1) {
    asm volatile(
        "mma.sync.aligned.m16n8k16.row.col.f32.bf16.bf16.f32 "
        "{%0,%1,%2,%3}, {%4,%5,%6,%7}, {%8,%9}, {%0,%1,%2,%3};"
        : "+f"(d[0]), "+f"(d[1]), "+f"(d[2]), "+f"(d[3])
        : "r"(a[0]), "r"(a[1]), "r"(a[2]), "r"(a[3]), "r"(b0), "r"(b1));
}
__device__ __forceinline__ void split2(float v, __nv_bfloat16& h, __nv_bfloat16& l) {
    h = __float2bfloat16(v);
    l = __float2bfloat16(v - __bfloat162float(h));
}

// ---------------- conversion kernels ----------------
__global__ void __launch_bounds__(256) convert_split_kernel(
    const float* __restrict__ src, __nv_bfloat16* __restrict__ hi,
    __nv_bfloat16* __restrict__ lo, size_t n4)
{
    size_t i = (size_t)blockIdx.x * 256 + threadIdx.x;
    if (i >= n4) return;
    float4 v = reinterpret_cast<const float4*>(src)[i];
    __nv_bfloat16 h0, h1, h2, h3, l0, l1, l2, l3;
    split2(v.x, h0, l0); split2(v.y, h1, l1); split2(v.z, h2, l2); split2(v.w, h3, l3);
    __nv_bfloat162 ph0{h0, h1}, ph1{h2, h3}, pl0{l0, l1}, pl1{l2, l3};
    uint2 uh{*reinterpret_cast<uint32_t*>(&ph0), *reinterpret_cast<uint32_t*>(&ph1)};
    uint2 ul{*reinterpret_cast<uint32_t*>(&pl0), *reinterpret_cast<uint32_t*>(&pl1)};
    reinterpret_cast<uint2*>(hi)[i] = uh;
    reinterpret_cast<uint2*>(lo)[i] = ul;
}

// transpose W [K][N] -> W^T split [N][K]
__global__ void __launch_bounds__(256) wsplit_t_kernel(
    const float* __restrict__ w, __nv_bfloat16* __restrict__ hi,
    __nv_bfloat16* __restrict__ lo, int K, int N)
{
    int idx = blockIdx.x * 256 + threadIdx.x;
    if (idx >= N * K) return;
    int n = idx / K, k = idx - n * K;
    float v = w[(size_t)k * N + n];
    __nv_bfloat16 h, l;
    split2(v, h, l);
    hi[idx] = h; lo[idx] = l;
}

// ---------------- mma.sync 3xbf16 GEMM: C = A @ B^T + bias -----------------
// A_{hi,lo}: [M][K] bf16, B_{hi,lo}: [N][K] bf16, C: [M][N] fp32.
// 128x128x64 tiles, 8 warps (4x2), warp tile 32x64, cp.async double buffer.
// SMEM stage layout: Ah(16K) Al(16K) Bh(16K) Bl(16K); rows 128B pitch,
// chunk swizzle: 16B chunk c of row r stored at (c ^ (r&7)).
#define STAGE_BYTES 65536
#define GEMM_SMEM   (2 * STAGE_BYTES)

__device__ __forceinline__ uint32_t sw_addr(uint32_t base, int row, int chunk) {
    return base + row * 128 + ((chunk ^ (row & 7)) << 4);
}

__global__ void __launch_bounds__(256, 1) gemm3_kernel(
    const __nv_bfloat16* __restrict__ Ah, const __nv_bfloat16* __restrict__ Al,
    const __nv_bfloat16* __restrict__ Bh, const __nv_bfloat16* __restrict__ Bl,
    const float* __restrict__ bias, float* __restrict__ C,
    int M, int N, int K)
{
    extern __shared__ char smem[];
    const uint32_t sbase = smem_to_u32(smem);
    const int tid  = threadIdx.x;
    const int lane = tid & 31;
    const int wid  = tid >> 5;
    const int warp_m = wid & 3;        // 4 warps in M: 32 rows each
    const int warp_n = wid >> 2;       // 2 warps in N: 64 cols each
    const int m0 = blockIdx.y * 128;
    const int n0 = blockIdx.x * 128;
    const int NKT = K >> 6;

    float acc[2][8][4];
    #pragma unroll
    for (int i = 0; i < 2; i++)
        #pragma unroll
        for (int j = 0; j < 8; j++)
            #pragma unroll
            for (int t = 0; t < 4; t++) acc[i][j][t] = 0.f;

    // per-thread load coords: 128 rows x 8 chunks per tensor, 4 per thread
    auto load_stage = [&](int kt, int s) {
        const uint32_t sb = sbase + s * STAGE_BYTES;
        const int kofs = kt * 64;
        #pragma unroll
        for (int i = 0; i < 4; i++) {
            int f   = tid + i * 256;
            int row = f >> 3;
            int c   = f & 7;
            uint32_t sw = sw_addr(0, row, c);
            size_t ga = (size_t)(m0 + row) * K + kofs + c * 8;
            size_t gb = (size_t)(n0 + row) * K + kofs + c * 8;
            cp_async16(sb + sw,         Ah + ga);
            cp_async16(sb + 16384 + sw, Al + ga);
            cp_async16(sb + 32768 + sw, Bh + gb);
            cp_async16(sb + 49152 + sw, Bl + gb);
        }
        CP_COMMIT();
    };

    load_stage(0, 0);

    for (int kt = 0; kt < NKT; kt++) {
        const int s = kt & 1;
        CP_WAIT0();
        __syncthreads();
        if (kt + 1 < NKT) load_stage(kt + 1, s ^ 1);

        const uint32_t sA = sbase + s * STAGE_BYTES;
        const uint32_t sB = sA + 32768;

        #pragma unroll
        for (int ks = 0; ks < 4; ks++) {
            // ---- A fragments (hi, lo) for 2 m-tiles ----
            uint32_t ah[2][4], al[2][4];
            {
                const int arow = warp_m * 32 + (lane & 15);
                const int achk = 2 * ks + (lane >> 4);
                #pragma unroll
                for (int mt = 0; mt < 2; mt++) {
                    uint32_t ad = sw_addr(sA, arow + mt * 16, achk);
                    ldsm4(ah[mt], ad);
                    ldsm4(al[mt], ad + 16384);
                }
            }
            // ---- B fragments (hi, lo): 4 x4-loads cover 8 n-tiles ----
            uint32_t bh[4][4], bl[4][4];
            {
                const int brow_base = warp_n * 64 + ((lane & 16) ? 8 : 0) + (lane & 7);
                const int bchk = 2 * ks + ((lane >> 3) & 1);
                #pragma unroll
                for (int p = 0; p < 4; p++) {
                    uint32_t bd = sw_addr(sB, brow_base + p * 16, bchk);
                    ldsm4(bh[p], bd);
                    ldsm4(bl[p], bd + 16384);
                }
            }
            // ---- 3-term MMAs ----
            #pragma unroll
            for (int mt = 0; mt < 2; mt++)
                #pragma unroll
                for (int p = 0; p < 4; p++)
                    #pragma unroll
                    for (int hlf = 0; hlf < 2; hlf++) {
                        const int nt = p * 2 + hlf;
                        mma16816(acc[mt][nt], ah[mt], bh[p][hlf*2], bh[p][hlf*2+1]);
                        mma16816(acc[mt][nt], ah[mt], bl[p][hlf*2], bl[p][hlf*2+1]);
                        mma16816(acc[mt][nt], al[mt], bh[p][hlf*2], bh[p][hlf*2+1]);
                    }
        }
        __syncthreads();
    }

    // ---- epilogue: warp covers rows [m0+warp_m*32, +32), cols [n0+warp_n*64, +64)
    const int row0 = m0 + warp_m * 32 + (lane >> 2);
    const int col0 = n0 + warp_n * 64 + (lane & 3) * 2;
    #pragma unroll
    for (int mt = 0; mt < 2; mt++)
        #pragma unroll
        for (int nt = 0; nt < 8; nt++) {
            const int c = col0 + nt * 8;
            const float b0 = bias[c], b1 = bias[c + 1];
            const int r0 = row0 + mt * 16;
            float2 v0{acc[mt][nt][0] + b0, acc[mt][nt][1] + b1};
            float2 v1{acc[mt][nt][2] + b0, acc[mt][nt][3] + b1};
            *reinterpret_cast<float2*>(C + (size_t)r0 * N + c)       = v0;
            *reinterpret_cast<float2*>(C + (size_t)(r0 + 8) * N + c) = v1;
        }
}

// ---------------- fused window attention (fp32 in, bf16 hi/lo out) ---------
__global__ void __launch_bounds__(128) attn_kernel(
    const float* __restrict__ qkv, const float* __restrict__ mask,
    const float* __restrict__ bias_table, const int* __restrict__ rel_idx,
    __nv_bfloat16* __restrict__ out_hi, __nv_bfloat16* __restrict__ out_lo)
{
    const int b = blockIdx.x;
    const int h = blockIdx.y;
    const int tid = threadIdx.x;

    __shared__ float qs[NTOK * HDIM];
    __shared__ float kt[HDIM * NTOK];
    __shared__ float vs[NTOK * HDIM];
    __shared__ float s [NTOK * 50];

    const float scale = 0.17677669529663687f;

    for (int idx = tid; idx < NTOK * 8; idx += 128) {
        int n  = idx >> 3;
        int c4 = (idx & 7) << 2;
        size_t base = ((size_t)(b * NTOK + n)) * QKV_N + h * HDIM + c4;
        float4 qv = *reinterpret_cast<const float4*>(qkv + base);
        float4 kv = *reinterpret_cast<const float4*>(qkv + base + DIMC);
        float4 vv = *reinterpret_cast<const float4*>(qkv + base + 2 * DIMC);
        *reinterpret_cast<float4*>(&qs[n * HDIM + c4]) = qv;
        *reinterpret_cast<float4*>(&vs[n * HDIM + c4]) = vv;
        kt[(c4 + 0) * NTOK + n] = kv.x;
        kt[(c4 + 1) * NTOK + n] = kv.y;
        kt[(c4 + 2) * NTOK + n] = kv.z;
        kt[(c4 + 3) * NTOK + n] = kv.w;
    }
    __syncthreads();

    const float* mrow = mask + (size_t)(b & (NWIN - 1)) * NTOK * NTOK;
    for (int e = tid; e < NTOK * NTOK; e += 128) {
        int n = e / NTOK;
        int m = e - n * NTOK;
        float acc = 0.f;
        #pragma unroll
        for (int kk = 0; kk < HDIM; kk++)
            acc += qs[n * HDIM + kk] * kt[kk * NTOK + m];
        s[n * 50 + m] = acc * scale + bias_table[rel_idx[e] * NHEAD + h] + mrow[e];
    }
    __syncthreads();

    if (tid < NTOK) {
        const int r = tid;
        float mx = -1e30f;
        for (int m = 0; m < NTOK; m++) mx = fmaxf(mx, s[r * 50 + m]);
        float sum = 0.f;
        for (int m = 0; m < NTOK; m++) {
            float e = expf(s[r * 50 + m] - mx);
            s[r * 50 + m] = e;
            sum += e;
        }
        float inv = 1.f / sum;
        for (int m = 0; m < NTOK; m++) s[r * 50 + m] *= inv;
    }
    __syncthreads();

    for (int o = tid; o < NTOK * HDIM; o += 128) {
        int n = o >> 5;
        int d = o & 31;
        float acc = 0.f;
        #pragma unroll
        for (int m = 0; m < NTOK; m++)
            acc += s[n * 50 + m] * vs[m * HDIM + d];
        size_t oi = ((size_t)(b * NTOK + n)) * DIMC + h * HDIM + d;
        __nv_bfloat16 hb, lb;
        split2(acc, hb, lb);
        out_hi[oi] = hb;
        out_lo[oi] = lb;
    }
}

// ---------------- launcher ----------------
extern "C" void kernel_launch(void* const* d_in, const int* in_sizes, int n_in,
                              void* d_out, int out_size)
{
    const float* x          = (const float*)d_in[0];
    const float* mask       = (const float*)d_in[1];
    const float* qkv_w      = (const float*)d_in[2];
    const float* qkv_b      = (const float*)d_in[3];
    const float* proj_w     = (const float*)d_in[4];
    const float* proj_b     = (const float*)d_in[5];
    const float* bias_table = (const float*)d_in[6];
    const int*   rel_idx    = (const int*)d_in[7];
    float* out = (float*)d_out;

    float *qkv;
    __nv_bfloat16 *xhi, *xlo, *ahi, *alo, *wqh, *wql, *wph, *wpl;
    cudaGetSymbolAddress((void**)&qkv, g_qkv);
    cudaGetSymbolAddress((void**)&xhi, g_xhi);
    cudaGetSymbolAddress((void**)&xlo, g_xlo);
    cudaGetSymbolAddress((void**)&ahi, g_ahi);
    cudaGetSymbolAddress((void**)&alo, g_alo);
    cudaGetSymbolAddress((void**)&wqh, g_wq_hi);
    cudaGetSymbolAddress((void**)&wql, g_wq_lo);
    cudaGetSymbolAddress((void**)&wph, g_wp_hi);
    cudaGetSymbolAddress((void**)&wpl, g_wp_lo);

    cudaFuncSetAttribute(gemm3_kernel, cudaFuncAttributeMaxDynamicSharedMemorySize, GEMM_SMEM);

    // 0) precompute splits
    size_t n4 = (size_t)M_TOTAL * DIMC / 4;
    convert_split_kernel<<<(unsigned)((n4 + 255) / 256), 256>>>(x, xhi, xlo, n4);
    wsplit_t_kernel<<<(QKV_N * DIMC + 255) / 256, 256>>>(qkv_w, wqh, wql, DIMC, QKV_N);
    wsplit_t_kernel<<<(DIMC * DIMC + 255) / 256, 256>>>(proj_w, wph, wpl, DIMC, DIMC);

    // 1) QKV projection: [100352 x 512] @ [512 x 1536] + b
    dim3 g1(QKV_N / 128, M_TOTAL / 128);
    gemm3_kernel<<<g1, 256, GEMM_SMEM>>>(xhi, xlo, wqh, wql, qkv_b, qkv,
                                         M_TOTAL, QKV_N, DIMC);

    // 2) fused window attention -> bf16 hi/lo
    dim3 g2(NB, NHEAD);
    attn_kernel<<<g2, 128>>>(qkv, mask, bias_table, rel_idx, ahi, alo);

    // 3) output projection: [100352 x 512] @ [512 x 512] + b
    dim3 g3(DIMC / 128, M_TOTAL / 128);
    gemm3_kernel<<<g3, 256, GEMM_SMEM>>>(ahi, alo, wph, wpl, proj_b, out,
                                         M_TOTAL, DIMC, DIMC);
}